// round 17
// baseline (speedup 1.0000x reference)
#include <cuda_runtime.h>
#include <cuda_bf16.h>
#include <cstdint>
#include <math.h>

#define NTH 512
#define TB  64

// ---- smem byte offsets ----
#define SB_X    0        // activation tile: hi 128x272, lo 128x272
#define SB_WH   69632
#define SB_WL   104448
#define SB_W3H  139264
#define SB_W3L  145408
#define SB_W1R  151552   // 12288: W1 split OR W1 fp32
#define SB_XTH  163840   // trig tile hi 64x48
#define SB_XTL  166912
#define SB_DY0  169984   // 128 x 25 f32
#define SB_DY1  182784   // 128 x 25 f32 (also gx buf 64x49 in tail)
#define SB_XF   195584   // 64 x 13
#define SB_Q    198912   // 64 x 7
#define SB_QD   200704
#define SB_AA   202496
#define SB_LR   204288   // 64 x 21
#define SB_MS   209664
#define SB_PH   215040   // 64 x 37: wv,Aacc,svec,Cacc,k1,k2
#define SB_B    224512
#define SB_END  227168

#define MMA(acc,a0,a1,a2,a3,b0,b1) \
  asm volatile("mma.sync.aligned.m16n8k16.row.col.f32.bf16.bf16.f32 " \
    "{%0,%1,%2,%3},{%4,%5,%6,%7},{%8,%9},{%0,%1,%2,%3};" \
    : "+f"(acc[0]),"+f"(acc[1]),"+f"(acc[2]),"+f"(acc[3]) \
    : "r"(a0),"r"(a1),"r"(a2),"r"(a3),"r"(b0),"r"(b1))

__device__ __forceinline__ void ldsm4(uint32_t& d0, uint32_t& d1, uint32_t& d2,
                                      uint32_t& d3, uint32_t addr) {
    asm volatile("ldmatrix.sync.aligned.m8n8.x4.shared.b16 {%0,%1,%2,%3},[%4];"
        : "=r"(d0), "=r"(d1), "=r"(d2), "=r"(d3) : "r"(addr));
}
__device__ __forceinline__ void ldsm4t(uint32_t& d0, uint32_t& d1, uint32_t& d2,
                                       uint32_t& d3, uint32_t addr) {
    asm volatile("ldmatrix.sync.aligned.m8n8.x4.trans.shared.b16 {%0,%1,%2,%3},[%4];"
        : "=r"(d0), "=r"(d1), "=r"(d2), "=r"(d3) : "r"(addr));
}
__device__ __forceinline__ void ldsm2t(uint32_t& d0, uint32_t& d1, uint32_t addr) {
    asm volatile("ldmatrix.sync.aligned.m8n8.x2.trans.shared.b16 {%0,%1},[%2];"
        : "=r"(d0), "=r"(d1) : "r"(addr));
}
static __device__ __forceinline__ float softplusf(float z) {
    return fmaxf(z, 0.0f) + __logf(1.0f + __expf(-fabsf(z)));
}
static __device__ __forceinline__ uint32_t pack2(float a, float b) {
    __nv_bfloat162 t = __floats2bfloat162_rn(a, b);
    return *reinterpret_cast<uint32_t*>(&t);
}
static __device__ __forceinline__ void wsplit2(float v, char* hi, char* lo, uint32_t off) {
    __nv_bfloat16 h = __float2bfloat16(v);
    *(__nv_bfloat16*)(hi + off) = h;
    *(__nv_bfloat16*)(lo + off) = __float2bfloat16(v - __bfloat162float(h));
}

extern "C" __global__ void __launch_bounds__(NTH, 1)
lnn_mma(const float* __restrict__ o,    const float* __restrict__ ain,
        const float* __restrict__ gW1L, const float* __restrict__ gb1L,
        const float* __restrict__ gW2L, const float* __restrict__ gb2L,
        const float* __restrict__ gW3L, const float* __restrict__ gb3L,
        const float* __restrict__ gW1V, const float* __restrict__ gb1V,
        const float* __restrict__ gW2V, const float* __restrict__ gb2V,
        const float* __restrict__ gW3V,
        float* __restrict__ outp, int B)
{
    extern __shared__ char smc[];
    float* W1f = (float*)(smc + SB_W1R);
    float* sXF = (float*)(smc + SB_XF);
    float* sQ  = (float*)(smc + SB_Q);
    float* sQD = (float*)(smc + SB_QD);
    float* sAA = (float*)(smc + SB_AA);
    float* sLr = (float*)(smc + SB_LR);
    float* sMs = (float*)(smc + SB_MS);
    float* sPH = (float*)(smc + SB_PH);
    float* sB  = (float*)(smc + SB_B);
    float* dy0 = (float*)(smc + SB_DY0);
    float* dy1 = (float*)(smc + SB_DY1);

    const int tid = threadIdx.x, w = tid >> 5, lane = tid & 31;
    const int gid = lane >> 2, tig = lane & 3;
    const int mt = w & 3, nq = w >> 2;
    const int r0 = mt * 16 + gid, r1 = r0 + 8;
    const int base = blockIdx.x * TB;
    const int RO[6] = {0, 1, 3, 6, 10, 15};
    #define MML(i,j) ((i)>=(j) ? Msl[RO[i]+(j)] : Msl[RO[j]+(i)])

    const uint32_t sbs = (uint32_t)__cvta_generic_to_shared(smc);
    const int fr = (lane & 7) + ((lane >> 3) & 1) * 8;   // frag row
    const int colA = (lane >> 4) * 16;
    const uint32_t aF = sbs + SB_X + (mt * 16 + fr) * 272 + colA;  // half0 A frag
    const int rowK = fr;
    const int colT = colA;
    const uint32_t bTH = sbs + SB_WH + rowK * 272 + nq * 64 + colT;
    const uint32_t bTL = sbs + SB_WL + rowK * 272 + nq * 64 + colT;
    const int rowBl = (lane & 7) + ((lane >> 4) << 3);
    const int colB  = ((lane >> 3) & 1) * 16;
    const uint32_t bVH0 = sbs + SB_WH + (nq * 32 + rowBl) * 272 + colB;
    const uint32_t bVH1 = bVH0 + 16 * 272;
    const uint32_t bVL0 = sbs + SB_WL + (nq * 32 + rowBl) * 272 + colB;
    const uint32_t bVL1 = bVL0 + 16 * 272;
    const uint32_t mTH = sbs + SB_W3H + rowK * 48 + colT;
    const uint32_t mTL = sbs + SB_W3L + rowK * 48 + colT;
    const uint32_t mTH2 = sbs + SB_W3H + rowK * 48 + 32;
    const uint32_t mTL2 = sbs + SB_W3L + rowK * 48 + 32;
    const uint32_t xAddrH = sbs + SB_XTH + (mt * 16 + fr) * 48 + colA;
    const uint32_t xAddrL = sbs + SB_XTL + (mt * 16 + fr) * 48 + colA;
    const uint32_t uAddrH0 = sbs + SB_W1R + (nq * 32 + rowBl) * 48 + colB;
    const uint32_t uAddrH1 = uAddrH0 + 16 * 48;
    const uint32_t uAddrL0 = uAddrH0 + 6144;
    const uint32_t uAddrL1 = uAddrH1 + 6144;

    // persistent loads
    for (int i = tid; i < 128; i += NTH) {
        sB[i] = gb1L[i]; sB[128 + i] = gb2L[i];
        sB[256 + i] = gb1V[i]; sB[384 + i] = gb2V[i]; sB[512 + i] = gW3V[i];
    }
    if (tid < 24) sB[640 + tid] = tid < 21 ? gb3L[tid] : 0.f;
    for (int i = tid; i < 3072; i += NTH) {     // W3 raw tile [c][t]
        int c = i / 24, t = i - c * 24;
        float v = (t < 21) ? gW3L[c * 21 + t] : 0.f;
        wsplit2(v, smc + SB_W3H, smc + SB_W3L, (uint32_t)(c * 48 + t * 2));
    }
    for (int i = tid; i < TB * 6; i += NTH) {
        int r = i / 6, c = i - 6 * r;
        int g = base + r; if (g > B - 1) g = B - 1;
        sQ[r * 7 + c] = o[g * 18 + c];
        sQD[r * 7 + c] = o[g * 18 + 6 + c];
        sAA[r * 7 + c] = ain[g * 6 + c];
    }

    float sg1[4][4], sg2[4][4];

    // ---- helpers ----
    auto storeA = [&](uint32_t halfOff, int nt, float v0, float v1, float v2, float v3) {
        uint32_t* H = (uint32_t*)(smc + SB_X + halfOff);
        uint32_t* L = (uint32_t*)(smc + SB_X + 34816 + halfOff);
        int ci = nq * 16 + nt * 4 + tig;
        uint32_t h01 = pack2(v0, v1);
        __nv_bfloat162 hh = *reinterpret_cast<__nv_bfloat162*>(&h01);
        H[r0 * 68 + ci] = h01;
        L[r0 * 68 + ci] = pack2(v0 - __bfloat162float(hh.x), v1 - __bfloat162float(hh.y));
        uint32_t h23 = pack2(v2, v3);
        __nv_bfloat162 hh2 = *reinterpret_cast<__nv_bfloat162*>(&h23);
        H[r1 * 68 + ci] = h23;
        L[r1 * 68 + ci] = pack2(v2 - __bfloat162float(hh2.x), v3 - __bfloat162float(hh2.y));
    };
    auto gemm64 = [&](float (&acc)[4][4], bool fwd, int rowBase) {
        const uint32_t aH = aF + rowBase * 272, aL = aH + 34816;
        #pragma unroll
        for (int nt = 0; nt < 4; nt++)
            acc[nt][0] = acc[nt][1] = acc[nt][2] = acc[nt][3] = 0.f;
        #pragma unroll
        for (int kt = 0; kt < 8; kt++) {
            uint32_t ah0, ah1, ah2, ah3, al0, al1, al2, al3;
            ldsm4(ah0, ah1, ah2, ah3, aH + kt * 32);
            ldsm4(al0, al1, al2, al3, aL + kt * 32);
            uint32_t bh[8], bl[8];
            if (fwd) {
                ldsm4t(bh[0], bh[1], bh[2], bh[3], bTH + kt * 4352);
                ldsm4t(bh[4], bh[5], bh[6], bh[7], bTH + kt * 4352 + 32);
                ldsm4t(bl[0], bl[1], bl[2], bl[3], bTL + kt * 4352);
                ldsm4t(bl[4], bl[5], bl[6], bl[7], bTL + kt * 4352 + 32);
            } else {
                ldsm4(bh[0], bh[1], bh[2], bh[3], bVH0 + kt * 32);
                ldsm4(bh[4], bh[5], bh[6], bh[7], bVH1 + kt * 32);
                ldsm4(bl[0], bl[1], bl[2], bl[3], bVL0 + kt * 32);
                ldsm4(bl[4], bl[5], bl[6], bl[7], bVL1 + kt * 32);
            }
            #pragma unroll
            for (int nt = 0; nt < 4; nt++) MMA(acc[nt], ah0, ah1, ah2, ah3, bh[nt*2], bh[nt*2+1]);
            #pragma unroll
            for (int nt = 0; nt < 4; nt++) MMA(acc[nt], ah0, ah1, ah2, ah3, bl[nt*2], bl[nt*2+1]);
            #pragma unroll
            for (int nt = 0; nt < 4; nt++) MMA(acc[nt], al0, al1, al2, al3, bh[nt*2], bh[nt*2+1]);
        }
    };
    auto gemm128 = [&](float (&accA)[4][4], float (&accB)[4][4]) {
        const uint32_t aH = aF, aL = aF + 34816;
        const uint32_t aHb = aF + 17408, aLb = aHb + 34816;
        #pragma unroll
        for (int nt = 0; nt < 4; nt++) {
            accA[nt][0] = accA[nt][1] = accA[nt][2] = accA[nt][3] = 0.f;
            accB[nt][0] = accB[nt][1] = accB[nt][2] = accB[nt][3] = 0.f;
        }
        #pragma unroll
        for (int kt = 0; kt < 8; kt++) {
            uint32_t pa[4], qa[4], pb[4], qb[4];
            ldsm4(pa[0], pa[1], pa[2], pa[3], aH + kt * 32);
            ldsm4(qa[0], qa[1], qa[2], qa[3], aL + kt * 32);
            ldsm4(pb[0], pb[1], pb[2], pb[3], aHb + kt * 32);
            ldsm4(qb[0], qb[1], qb[2], qb[3], aLb + kt * 32);
            uint32_t bh[8], bl[8];
            ldsm4t(bh[0], bh[1], bh[2], bh[3], bTH + kt * 4352);
            ldsm4t(bh[4], bh[5], bh[6], bh[7], bTH + kt * 4352 + 32);
            ldsm4t(bl[0], bl[1], bl[2], bl[3], bTL + kt * 4352);
            ldsm4t(bl[4], bl[5], bl[6], bl[7], bTL + kt * 4352 + 32);
            #pragma unroll
            for (int nt = 0; nt < 4; nt++) MMA(accA[nt], pa[0], pa[1], pa[2], pa[3], bh[nt*2], bh[nt*2+1]);
            #pragma unroll
            for (int nt = 0; nt < 4; nt++) MMA(accB[nt], pb[0], pb[1], pb[2], pb[3], bh[nt*2], bh[nt*2+1]);
            #pragma unroll
            for (int nt = 0; nt < 4; nt++) MMA(accA[nt], pa[0], pa[1], pa[2], pa[3], bl[nt*2], bl[nt*2+1]);
            #pragma unroll
            for (int nt = 0; nt < 4; nt++) MMA(accB[nt], pb[0], pb[1], pb[2], pb[3], bl[nt*2], bl[nt*2+1]);
            #pragma unroll
            for (int nt = 0; nt < 4; nt++) MMA(accA[nt], qa[0], qa[1], qa[2], qa[3], bh[nt*2], bh[nt*2+1]);
            #pragma unroll
            for (int nt = 0; nt < 4; nt++) MMA(accB[nt], qb[0], qb[1], qb[2], qb[3], bh[nt*2], bh[nt*2+1]);
        }
    };
    auto l1Gemm = [&](float (&acc)[4][4]) {
        uint32_t ah0, ah1, ah2, ah3, al0, al1, al2, al3;
        ldsm4(ah0, ah1, ah2, ah3, xAddrH);
        ldsm4(al0, al1, al2, al3, xAddrL);
        uint32_t bh[8], bl[8];
        ldsm4(bh[0], bh[1], bh[2], bh[3], uAddrH0);
        ldsm4(bh[4], bh[5], bh[6], bh[7], uAddrH1);
        ldsm4(bl[0], bl[1], bl[2], bl[3], uAddrL0);
        ldsm4(bl[4], bl[5], bl[6], bl[7], uAddrL1);
        #pragma unroll
        for (int nt = 0; nt < 4; nt++)
            acc[nt][0] = acc[nt][1] = acc[nt][2] = acc[nt][3] = 0.f;
        #pragma unroll
        for (int nt = 0; nt < 4; nt++) MMA(acc[nt], ah0, ah1, ah2, ah3, bh[nt*2], bh[nt*2+1]);
        #pragma unroll
        for (int nt = 0; nt < 4; nt++) MMA(acc[nt], ah0, ah1, ah2, ah3, bl[nt*2], bl[nt*2+1]);
        #pragma unroll
        for (int nt = 0; nt < 4; nt++) MMA(acc[nt], al0, al1, al2, al3, bh[nt*2], bh[nt*2+1]);
    };
    // mini over nw warps starting at warp 8; A rows = aRowBase + (w-8)*16
    auto miniGemm = [&](int aRowBase, int nw, float* dyOut) {
        if (w < 8 || w >= 8 + nw) return;
        int w8 = w - 8;
        const uint32_t aH = sbs + SB_X + (aRowBase + w8 * 16 + fr) * 272 + colA;
        const uint32_t aL = aH + 34816;
        float acc[3][4];
        #pragma unroll
        for (int nt = 0; nt < 3; nt++)
            acc[nt][0] = acc[nt][1] = acc[nt][2] = acc[nt][3] = 0.f;
        #pragma unroll
        for (int kt = 0; kt < 8; kt++) {
            uint32_t ah0, ah1, ah2, ah3, al0, al1, al2, al3;
            ldsm4(ah0, ah1, ah2, ah3, aH + kt * 32);
            ldsm4(al0, al1, al2, al3, aL + kt * 32);
            uint32_t bh[6], bl[6];
            ldsm4t(bh[0], bh[1], bh[2], bh[3], mTH + kt * 768);
            ldsm2t(bh[4], bh[5], mTH2 + kt * 768);
            ldsm4t(bl[0], bl[1], bl[2], bl[3], mTL + kt * 768);
            ldsm2t(bl[4], bl[5], mTL2 + kt * 768);
            #pragma unroll
            for (int nt = 0; nt < 3; nt++) MMA(acc[nt], ah0, ah1, ah2, ah3, bh[nt*2], bh[nt*2+1]);
            #pragma unroll
            for (int nt = 0; nt < 3; nt++) MMA(acc[nt], ah0, ah1, ah2, ah3, bl[nt*2], bl[nt*2+1]);
            #pragma unroll
            for (int nt = 0; nt < 3; nt++) MMA(acc[nt], al0, al1, al2, al3, bh[nt*2], bh[nt*2+1]);
        }
        int rr0 = aRowBase + w8 * 16 + gid, rr1 = rr0 + 8;
        #pragma unroll
        for (int nt = 0; nt < 3; nt++) {
            int c = nt * 8 + tig * 2;
            dyOut[rr0 * 25 + c] = acc[nt][0]; dyOut[rr0 * 25 + c + 1] = acc[nt][1];
            dyOut[rr1 * 25 + c] = acc[nt][2]; dyOut[rr1 * 25 + c + 1] = acc[nt][3];
        }
    };
    auto buildU1pair = [&](int d0) {         // u1(d0)->half0, u1(d0+1)->half1
        #pragma unroll
        for (int hf = 0; hf < 2; hf++) {
            int d = d0 + hf;
            float cq0 = sXF[r0 * 13 + 2 * d], sq0 = sXF[r0 * 13 + 2 * d + 1];
            float cq1 = sXF[r1 * 13 + 2 * d], sq1 = sXF[r1 * 13 + 2 * d + 1];
            #pragma unroll
            for (int nt = 0; nt < 4; nt++) {
                int c = nq * 32 + nt * 8 + tig * 2;
                float2 wa = *(const float2*)&W1f[2 * d * 128 + c];
                float2 wb = *(const float2*)&W1f[(2 * d + 1) * 128 + c];
                storeA(hf * 17408, nt,
                    sg1[nt][0] * (cq0 * wb.x - sq0 * wa.x),
                    sg1[nt][1] * (cq0 * wb.y - sq0 * wa.y),
                    sg1[nt][2] * (cq1 * wb.x - sq1 * wa.x),
                    sg1[nt][3] * (cq1 * wb.y - sq1 * wa.y));
            }
        }
    };
    auto physicsStep = [&](int d, const float* dy) {   // tid<64; dy=row ptr
        float* ph = sPH + tid * 37;
        const float* Lp = sLr + tid * 21;
        float qdr[6];
        #pragma unroll
        for (int j = 0; j < 6; j++) qdr[j] = sQD[tid * 7 + j];
        float D6[6][6];
        #pragma unroll
        for (int i = 0; i < 6; i++)
            #pragma unroll
            for (int j = 0; j < 6; j++) if (j <= i) {
                float s2 = 0.f;
                #pragma unroll
                for (int k = 0; k < 6; k++) if (k <= j)
                    s2 += dy[RO[i] + k] * Lp[RO[j] + k] + Lp[RO[i] + k] * dy[RO[j] + k];
                D6[i][j] = s2; D6[j][i] = s2;
            }
        float qdd = qdr[d], cdot = 0.f;
        #pragma unroll
        for (int i = 0; i < 6; i++) {
            float v1 = 0.f, v2 = 0.f;
            #pragma unroll
            for (int j = 0; j < 6; j++) { v1 += D6[i][j] * ph[j]; v2 += D6[i][j] * qdr[j]; }
            ph[6 + i] += qdd * v1; ph[12 + i] += qdd * v2; cdot += qdr[i] * v1;
        }
        ph[18 + d] = cdot;
    };
    auto streamW2body = [&](const float* g, int t, int nt) {
        for (int i = t * 4; i < 16384; i += nt * 4) {
            float4 v = *(const float4*)&g[i];
            int r = i >> 7, c = i & 127;
            uint32_t h01 = pack2(v.x, v.y), h23 = pack2(v.z, v.w);
            __nv_bfloat162 a01 = *reinterpret_cast<__nv_bfloat162*>(&h01);
            __nv_bfloat162 a23 = *reinterpret_cast<__nv_bfloat162*>(&h23);
            uint32_t l01 = pack2(v.x - __bfloat162float(a01.x), v.y - __bfloat162float(a01.y));
            uint32_t l23 = pack2(v.z - __bfloat162float(a23.x), v.w - __bfloat162float(a23.y));
            *(uint2*)(smc + SB_WH + r * 272 + c * 2) = make_uint2(h01, h23);
            *(uint2*)(smc + SB_WL + r * 272 + c * 2) = make_uint2(l01, l23);
        }
    };
    auto streamW1Sbody = [&](const float* g, int t, int nt) {
        for (int i = t; i < 2048; i += nt) {
            int c = i >> 4, tt = i & 15;
            float v = (tt < 12) ? g[tt * 128 + c] : 0.f;
            wsplit2(v, smc + SB_W1R, smc + SB_W1R + 6144, (uint32_t)(c * 48 + tt * 2));
        }
    };
    auto actEpi = [&](float (&acc)[4][4], const float* bias, float (&sg)[4][4],
                      uint32_t halfOff) {
        #pragma unroll
        for (int nt = 0; nt < 4; nt++) {
            int c = nq * 32 + nt * 8 + tig * 2;
            float h0 = softplusf(acc[nt][0] + bias[c]);
            float h1 = softplusf(acc[nt][1] + bias[c + 1]);
            float h2 = softplusf(acc[nt][2] + bias[c]);
            float h3 = softplusf(acc[nt][3] + bias[c + 1]);
            sg[nt][0] = 1.f - __expf(-h0); sg[nt][1] = 1.f - __expf(-h1);
            sg[nt][2] = 1.f - __expf(-h2); sg[nt][3] = 1.f - __expf(-h3);
            storeA(halfOff, nt, h0, h1, h2, h3);
        }
    };

    __syncthreads();
    const float ADT = (2.0f / 3.0f) * 0.02f;

    for (int stage = 0; stage < 2; ++stage) {
        // HEAD: trig + streams
        if (tid < TB) {
            int r = tid;
            #pragma unroll
            for (int i = 0; i < 6; i++) {
                float sv, cv; __sincosf(sQ[r * 7 + i], &sv, &cv);
                sXF[r * 13 + 2 * i] = cv; sXF[r * 13 + 2 * i + 1] = sv;
            }
            #pragma unroll
            for (int t = 0; t < 12; t++)
                wsplit2(sXF[r * 13 + t], smc + SB_XTH, smc + SB_XTL, (uint32_t)(r * 48 + t * 2));
            ((uint32_t*)(smc + SB_XTH))[r * 12 + 6] = 0; ((uint32_t*)(smc + SB_XTH))[r * 12 + 7] = 0;
            ((uint32_t*)(smc + SB_XTL))[r * 12 + 6] = 0; ((uint32_t*)(smc + SB_XTL))[r * 12 + 7] = 0;
        }
        streamW2body(gW2L, tid, NTH);
        streamW1Sbody(gW1L, tid, NTH);
        __syncthreads();
        // layer1 L -> h1 (half0), sigma1
        { float acc[4][4]; l1Gemm(acc); actEpi(acc, sB, sg1, 0); }
        __syncthreads();
        for (int i = tid; i < 1536; i += NTH) W1f[i] = gW1L[i];   // W1f := W1L
        // h2 -> half1, sigma2
        { float acc[4][4]; gemm64(acc, true, 0); actEpi(acc, sB + 128, sg2, 17408); }
        __syncthreads();
        miniGemm(64, 4, dy1);                 // y -> dy1 rows 64..127
        __syncthreads();
        buildU1pair(0);                        // u1(0)->half0, u1(1)->half1
        __syncthreads();

        // ---- 3 pair-iterations ----
        for (int it = 0; it < 3; ++it) {
            float accA[4][4], accB[4][4];
            gemm128(accA, accB);               // u1 pair @ W2L^T
            __syncthreads();                   // all reads of X done
            #pragma unroll
            for (int nt = 0; nt < 4; nt++) {   // u2 pair -> X in place
                storeA(0, nt, accA[nt][0] * sg2[nt][0], accA[nt][1] * sg2[nt][1],
                       accA[nt][2] * sg2[nt][2], accA[nt][3] * sg2[nt][3]);
                storeA(17408, nt, accB[nt][0] * sg2[nt][0], accB[nt][1] * sg2[nt][1],
                       accB[nt][2] * sg2[nt][2], accB[nt][3] * sg2[nt][3]);
            }
            __syncthreads();
            // slot C: mini(pair) || physics(prev) || streams at it==2
            float* dyCur = (it & 1) ? dy1 : dy0;
            miniGemm(0, 8, dyCur);
            if (w < 2 && tid < TB) {
                if (it == 0) {                 // physics init from y (dy1 rows 64+)
                    int r = tid;
                    const float* dyy = dy1 + (64 + r) * 25;
                    float Lrl[21], Msl[21];
                    #pragma unroll
                    for (int t = 0; t < 21; t++) { Lrl[t] = dyy[t] + sB[640 + t]; sLr[r * 21 + t] = Lrl[t]; }
                    #pragma unroll
                    for (int i = 0; i < 6; i++)
                        #pragma unroll
                        for (int j = 0; j < 6; j++) if (j <= i) {
                            float s2 = 0.f;
                            #pragma unroll
                            for (int k = 0; k < 6; k++) if (k <= j) s2 += Lrl[RO[i] + k] * Lrl[RO[j] + k];
                            if (i == j) s2 += 1e-6f;
                            Msl[RO[i] + j] = s2; sMs[r * 21 + RO[i] + j] = s2;
                        }
                    float* ph = sPH + r * 37;
                    #pragma unroll
                    for (int i = 0; i < 6; i++) {
                        float s2 = 0.f;
                        #pragma unroll
                        for (int j = 0; j < 6; j++) s2 += MML(i, j) * sQD[r * 7 + j];
                        ph[i] = s2; ph[6 + i] = 0.f; ph[12 + i] = 0.f;
                    }
                } else {
                    float* dyP = (it & 1) ? dy0 : dy1;   // prev buffer
                    physicsStep(2 * (it - 1),     dyP + tid * 25);
                    physicsStep(2 * (it - 1) + 1, dyP + (64 + tid) * 25);
                }
            }
            if (it == 2 && w >= 2 && w < 8) {  // stream V weights (W2L dead)
                streamW2body(gW2V, tid - 64, 192);
                streamW1Sbody(gW1V, tid - 64, 192);
            }
            __syncthreads();
            if (it < 2) buildU1pair(2 * (it + 1));
            else { float acc[4][4]; l1Gemm(acc); actEpi(acc, sB + 256, sg1, 0); }  // h1V->half0
            __syncthreads();
        }

        // TAIL: physics(pair2) || W1f := W1V
        if (w < 2 && tid < TB) {
            physicsStep(4, dy0 + tid * 25);
            physicsStep(5, dy0 + (64 + tid) * 25);
        } else {
            for (int i = tid - 64; i >= 0 && i < 1536; i += NTH - 64) W1f[i] = gW1V[i];
        }
        __syncthreads();
        // h2V -> u2g (half1)
        {
            float acc[4][4]; gemm64(acc, true, 0);
            #pragma unroll
            for (int nt = 0; nt < 4; nt++) {
                int c = nq * 32 + nt * 8 + tig * 2;
                float h0 = softplusf(acc[nt][0] + sB[384 + c]);
                float h1 = softplusf(acc[nt][1] + sB[384 + c + 1]);
                float h2 = softplusf(acc[nt][2] + sB[384 + c]);
                float h3 = softplusf(acc[nt][3] + sB[384 + c + 1]);
                storeA(17408, nt, (1.f - __expf(-h0)) * sB[512 + c],
                       (1.f - __expf(-h1)) * sB[512 + c + 1],
                       (1.f - __expf(-h2)) * sB[512 + c],
                       (1.f - __expf(-h3)) * sB[512 + c + 1]);
            }
        }
        __syncthreads();
        // VJP GEMM (A = half1, non-trans B) + gx partials -> dy1 (stride 49)
        {
            float acc[4][4]; gemm64(acc, false, 64);
            float gx0[12], gx1[12];
            #pragma unroll
            for (int t = 0; t < 12; t++) { gx0[t] = 0.f; gx1[t] = 0.f; }
            #pragma unroll
            for (int nt = 0; nt < 4; nt++) {
                int c = nq * 32 + nt * 8 + tig * 2;
                float u0 = acc[nt][0] * sg1[nt][0], u1 = acc[nt][1] * sg1[nt][1];
                float u2 = acc[nt][2] * sg1[nt][2], u3 = acc[nt][3] * sg1[nt][3];
                #pragma unroll
                for (int t = 0; t < 12; t++) {
                    float2 wv2 = *(const float2*)&W1f[t * 128 + c];
                    gx0[t] += u0 * wv2.x + u1 * wv2.y;
                    gx1[t] += u2 * wv2.x + u3 * wv2.y;
                }
            }
            #pragma unroll
            for (int t = 0; t < 12; t++) {
                gx0[t] += __shfl_xor_sync(0xFFFFFFFF, gx0[t], 1);
                gx0[t] += __shfl_xor_sync(0xFFFFFFFF, gx0[t], 2);
                gx1[t] += __shfl_xor_sync(0xFFFFFFFF, gx1[t], 1);
                gx1[t] += __shfl_xor_sync(0xFFFFFFFF, gx1[t], 2);
            }
            __syncthreads();                      // dy1 free (physics pair2 done pre-tail)
            if (tig == 0) {
                #pragma unroll
                for (int t = 0; t < 12; t++) {
                    dy1[r0 * 49 + nq * 12 + t] = gx0[t];
                    dy1[r1 * 49 + nq * 12 + t] = gx1[t];
                }
            }
        }
        __syncthreads();
        // final per-row: cvec, rhs, solves, state update
        if (tid < TB) {
            int r = tid;
            float* ph = sPH + r * 37;
            float Msl[21];
            #pragma unroll
            for (int t = 0; t < 21; t++) Msl[t] = sMs[r * 21 + t];
            float cv[6];
            #pragma unroll
            for (int i = 0; i < 6; i++) {
                float ms = 0.f;
                #pragma unroll
                for (int j = 0; j < 6; j++) ms += MML(i, j) * ph[12 + j];
                cv[i] = ph[6 + i] + ms - ph[18 + i];
            }
            float rhs[6];
            #pragma unroll
            for (int i = 0; i < 6; i++) {
                float g0 = dy1[r * 49 + 2 * i]      + dy1[r * 49 + 12 + 2 * i]
                         + dy1[r * 49 + 24 + 2 * i] + dy1[r * 49 + 36 + 2 * i];
                float g1 = dy1[r * 49 + 2 * i + 1]      + dy1[r * 49 + 12 + 2 * i + 1]
                         + dy1[r * 49 + 24 + 2 * i + 1] + dy1[r * 49 + 36 + 2 * i + 1];
                float dv = -sXF[r * 13 + 2 * i + 1] * g0 + sXF[r * 13 + 2 * i] * g1;
                rhs[i] = sAA[r * 7 + i] - cv[i] - dv;
            }
            float yv[6], zv[6];
            #pragma unroll
            for (int i = 0; i < 6; i++) {
                float s2 = rhs[i];
                #pragma unroll
                for (int j = 0; j < 6; j++) if (j < i) s2 -= Msl[RO[i] + j] * yv[j];
                yv[i] = s2 / Msl[RO[i] + i];
            }
            #pragma unroll
            for (int ii = 5; ii >= 0; ii--) {
                float s2 = yv[ii];
                #pragma unroll
                for (int j = 0; j < 6; j++) if (j > ii) s2 -= Msl[RO[j] + ii] * zv[j];
                zv[ii] = s2 / Msl[RO[ii] + ii];
            }
            if (stage == 0) {
                #pragma unroll
                for (int i = 0; i < 6; i++) {
                    ph[24 + i] = zv[i];
                    float qdi = sQD[r * 7 + i];
                    sQ[r * 7 + i] += ADT * qdi;
                    sQD[r * 7 + i] = qdi + ADT * zv[i];
                }
            } else {
                #pragma unroll
                for (int i = 0; i < 6; i++) ph[30 + i] = zv[i];
            }
        }
        __syncthreads();
    }

    // ---- output ----
    if (tid < TB && base + tid < B) {
        int g = base + tid, r = tid;
        const float* ph = sPH + r * 37;
        #pragma unroll
        for (int i = 0; i < 6; i++)
            outp[g * 18 + i] = o[g * 18 + i]
                + 0.02f * (0.25f * o[g * 18 + 6 + i] + 0.75f * sQD[r * 7 + i]);
        #pragma unroll
        for (int i = 0; i < 6; i++)
            outp[g * 18 + 6 + i] = o[g * 18 + 6 + i]
                + 0.02f * (0.25f * ph[24 + i] + 0.75f * ph[30 + i]);
        #pragma unroll
        for (int i = 0; i < 6; i++)
            outp[g * 18 + 12 + i] = o[g * 18 + 12 + i];
    }
}

extern "C" void kernel_launch(void* const* d_in, const int* in_sizes, int n_in,
                              void* d_out, int out_size) {
    const float* o   = (const float*)d_in[0];
    const float* a   = (const float*)d_in[1];
    const float* W1L = (const float*)d_in[2];
    const float* b1L = (const float*)d_in[3];
    const float* W2L = (const float*)d_in[4];
    const float* b2L = (const float*)d_in[5];
    const float* W3L = (const float*)d_in[6];
    const float* b3L = (const float*)d_in[7];
    const float* W1V = (const float*)d_in[8];
    const float* b1V = (const float*)d_in[9];
    const float* W2V = (const float*)d_in[10];
    const float* b2V = (const float*)d_in[11];
    const float* W3V = (const float*)d_in[12];
    float* outp = (float*)d_out;

    int B = in_sizes[0] / 18;
    int grid = (B + TB - 1) / TB;
    cudaFuncSetAttribute(lnn_mma,
                         cudaFuncAttributeMaxDynamicSharedMemorySize, SB_END);
    lnn_mma<<<grid, NTH, SB_END>>>(o, a, W1L, b1L, W2L, b2L, W3L, b3L,
                                   W1V, b1V, W2V, b2V, W3V, outp, B);
}